// round 16
// baseline (speedup 1.0000x reference)
#include <cuda_runtime.h>

#define TT 128
#define BB 64
#define HH 128
#define EE0 128
#define EE1 64
#define TB (TT*BB)
#define BH (BB*HH)
#define LOG2E 1.4426950408889634f

// Scratch (device globals: no allocation allowed in kernel_launch)
__device__ float g_x1T[BB*HH*TT];   // x1 transposed [B,H,T]
__device__ float g_q[TT*BB*HH];     // x2, then q = x2 + cum(y)/(t+1)
__device__ float g_y[TT*BB*HH];     // in@w3, then in-chunk prefix sums
__device__ float g_ps[8*BH];        // per-chunk totals
__device__ float g_s[BB*TT*TT];     // scores [b][i][j] (diagonal-masked)
__device__ float g_ma[TT*BB*HH];    // m_a           [T,B,H]
__device__ float g_l1[4*EE1*TB];    // layer1 outs [pass*2+branch][c][row]

__device__ __forceinline__ float fex2(float x){ float r; asm("ex2.approx.f32 %0, %1;" : "=f"(r) : "f"(x)); return r; }
__device__ __forceinline__ float frcp(float x){ float r; asm("rcp.approx.f32 %0, %1;" : "=f"(r) : "f"(x)); return r; }
__device__ __forceinline__ float ftanh(float x){ float r; asm("tanh.approx.f32 %0, %1;" : "=f"(r) : "f"(x)); return r; }
__device__ __forceinline__ float sigmoidf_(float x){ return frcp(1.0f + fex2(x * -LOG2E)); }
__device__ __forceinline__ float leakyf_(float x){ return x > 0.0f ? x : 0.3f * x; }

// ---------------------------------------------------------------------------
// K1: triple GEMM, uniform K=128. grid (256, 3), 128 thr, 32 rows/block.
// (frozen R11)
// ---------------------------------------------------------------------------
__global__ __launch_bounds__(128) void k_gemm3(
    const float* __restrict__ in,
    const float* __restrict__ w1, const float* __restrict__ w1b,
    const float* __restrict__ w2, const float* __restrict__ w3)
{
    __shared__ float s_in[HH][36];      // 18.4KB input tile transposed
    __shared__ float s_w[2][8][128];    // 8KB double-buffered weight tile

    int tid  = threadIdx.x;
    int row0 = blockIdx.x * 32;
    int y    = blockIdx.y;              // 0: x1, 1: x2, 2: y

    const float* wsel = (y == 0) ? w1 : (y == 1) ? w2 : w3;

    for (int idx = tid; idx < 32 * HH; idx += 128) {
        int h = idx & 127, r = idx >> 7;
        s_in[h][r] = in[(row0 + r) * HH + h];
    }

    int cg = tid & 31;               // cols cg*4 .. cg*4+3  (== lane)
    int rg = tid >> 5;               // rows rg*8 .. rg*8+7  (== warp)
    float a0[32];
#pragma unroll
    for (int x = 0; x < 32; x++) a0[x] = 0.0f;

    const float4* kv = (const float4*)wsel;
    float4* swv = (float4*)&s_w[0][0][0];  // [2][8][32] float4 view
    swv[tid]       = kv[(tid >> 5) * 32 + (tid & 31)];
    swv[128 + tid] = kv[((128 + tid) >> 5) * 32 + (tid & 31)];
    __syncthreads();

    for (int t = 0; t < 16; t++) {
        int cb = t & 1, nb = cb ^ 1;
        if (t + 1 < 16) {
            int h0n = (t + 1) * 8;
#pragma unroll
            for (int kk = 0; kk < 2; kk++) {
                int lin = kk * 128 + tid;
                swv[nb * 256 + lin] = kv[(h0n + (lin >> 5)) * 32 + (lin & 31)];
            }
        }
        int h0 = t * 8;
#pragma unroll
        for (int hl = 0; hl < 8; hl++) {
            float4 w4 = swv[cb * 256 + hl * 32 + cg];
            float4 va = *(const float4*)&s_in[h0 + hl][rg * 8];
            float4 vb = *(const float4*)&s_in[h0 + hl][rg * 8 + 4];
            float wv[4] = {w4.x, w4.y, w4.z, w4.w};
            float rv[8] = {va.x, va.y, va.z, va.w, vb.x, vb.y, vb.z, vb.w};
#pragma unroll
            for (int cc = 0; cc < 4; cc++)
#pragma unroll
                for (int rr = 0; rr < 8; rr++)
                    a0[cc * 8 + rr] = fmaf(wv[cc], rv[rr], a0[cc * 8 + rr]);
        }
        __syncthreads();
    }

    if (y == 0) {
        float4 bv = *(const float4*)&w1b[cg * 4];
        float bb[4] = {bv.x, bv.y, bv.z, bv.w};
#pragma unroll
        for (int cc = 0; cc < 4; cc++) {
            int col = cg * 4 + cc;
#pragma unroll
            for (int rr = 0; rr < 8; rr++) {
                int grow = row0 + rg * 8 + rr;
                int tt = grow >> 6;       // row = t*B + b
                int b  = grow & 63;
                g_x1T[(b * HH + col) * TT + tt] = a0[cc * 8 + rr] + bb[cc];
            }
        }
    } else {
        float* dst = (y == 1) ? g_q : g_y;
#pragma unroll
        for (int rr = 0; rr < 8; rr++) {
            int grow = row0 + rg * 8 + rr;
            float4 v = make_float4(a0[0 * 8 + rr], a0[1 * 8 + rr],
                                   a0[2 * 8 + rr], a0[3 * 8 + rr]);
            *(float4*)&dst[grow * HH + cg * 4] = v;   // coalesced STG.128
        }
    }
}

// ---------------------------------------------------------------------------
// K2a: scan phase A (frozen R11).
// ---------------------------------------------------------------------------
__global__ __launch_bounds__(256) void k_qfixA() {
    int gid = blockIdx.x * 256 + threadIdx.x;   // 0..65535
    int c   = gid >> 13;                        // chunk 0..7
    int idx = gid & (BH - 1);                   // (b,h) 0..8191
    float acc = 0.0f;
#pragma unroll
    for (int k = 0; k < 16; k++) {
        int t = c * 16 + k;
        acc += g_y[t * BH + idx];
        g_y[t * BH + idx] = acc;                // local prefix incl. current
    }
    g_ps[c * BH + idx] = acc;                   // chunk total
}

// ---------------------------------------------------------------------------
// K2b: scan phase B (frozen R11).
// ---------------------------------------------------------------------------
__global__ __launch_bounds__(256) void k_qfixB() {
    int gid = blockIdx.x * 256 + threadIdx.x;   // 0..2^20-1
    int t   = gid >> 13;
    int idx = gid & (BH - 1);
    int c   = t >> 4;
    float off = 0.0f;
    for (int cc = 0; cc < c; cc++)
        off += g_ps[cc * BH + idx];
    float cum = off + g_y[gid];
    g_q[gid] += cum / (float)(t + 1);
}

// ---------------------------------------------------------------------------
// K3a v2: score tiles, 32x32. grid (10, 64): triangular over 4x4 tile grid.
// 256 threads = 1 i x 4 contiguous j each -> per h: 1 LDS.128 + 2 bcast LDS
// + 4x(FADD+tanh+FMA). Row pads x36 keep all float4 accesses 16B-aligned.
// ---------------------------------------------------------------------------
__global__ __launch_bounds__(256) void k_stile(const float* __restrict__ w0)
{
    __shared__ float sx1T[HH][36];    // 0.5*x1 tile, [h][j-local 0..31]
    __shared__ float sqT[HH][36];     // 0.5*q  tile, [h][i-local 0..31]
    __shared__ float w0s[HH];
    __shared__ float w0sum_sh;

    int tid = threadIdx.x;
    int b   = blockIdx.y;
    // triangular enumeration over 4 tile-rows: bx -> (it, jt), jt <= it
    int it = 0, x = blockIdx.x;
    while (x > it) { x -= it + 1; it++; }
    int jt = x;
    int i0 = it * 32, j0 = jt * 32;

    // load tiles (coalesced reads)
    {
        const float* xb = g_x1T + b * (HH * TT) + j0;   // [h][t], t=j0+jl
        for (int idx = tid; idx < HH * 32; idx += 256) {
            int h = idx >> 5, jl = idx & 31;
            sx1T[h][jl] = xb[h * TT + jl] * 0.5f;
        }
        for (int idx = tid; idx < 32 * HH; idx += 256) {
            int il = idx >> 7, h = idx & 127;           // h fastest: coalesced
            sqT[h][il] = g_q[((i0 + il) * BB + b) * HH + h] * 0.5f;
        }
    }
    if (tid < 128) w0s[tid] = w0[tid];
    __syncthreads();
    if (tid < 32) {
        float s = w0s[tid] + w0s[tid+32] + w0s[tid+64] + w0s[tid+96];
#pragma unroll
        for (int off = 16; off; off >>= 1) s += __shfl_xor_sync(0xFFFFFFFFu, s, off);
        if (tid == 0) w0sum_sh = s;
    }
    __syncthreads();

    int jq = tid & 7;                 // j group: cols jq*4 .. jq*4+3
    int il = tid >> 3;                // i row 0..31
    float acc[4] = {0.0f, 0.0f, 0.0f, 0.0f};
#pragma unroll 4
    for (int h = 0; h < HH; h++) {
        float4 x4 = *(const float4*)&sx1T[h][jq * 4];   // 8 chunks/warp: conflict-free
        float qv  = sqT[h][il];                         // broadcast
        float wv  = w0s[h];                             // broadcast
        acc[0] = fmaf(wv, ftanh(x4.x + qv), acc[0]);
        acc[1] = fmaf(wv, ftanh(x4.y + qv), acc[1]);
        acc[2] = fmaf(wv, ftanh(x4.z + qv), acc[2]);
        acc[3] = fmaf(wv, ftanh(x4.w + qv), acc[3]);
    }
    float w0sum = w0sum_sh;
    int gi = i0 + il;
    int gjb = j0 + jq * 4;
    float4 v;
    v.x = (gjb + 0 <= gi) ? 0.5f * (acc[0] + w0sum) : 0.0f;
    v.y = (gjb + 1 <= gi) ? 0.5f * (acc[1] + w0sum) : 0.0f;
    v.z = (gjb + 2 <= gi) ? 0.5f * (acc[2] + w0sum) : 0.0f;
    v.w = (gjb + 3 <= gi) ? 0.5f * (acc[3] + w0sum) : 0.0f;
    *(float4*)&g_s[(b * TT + gi) * TT + gjb] = v;       // coalesced STG.128
}

// ---------------------------------------------------------------------------
// K3b: m_a = scores @ in (batched triangular GEMM). grid (8, 64): 16 i-rows
// per block per b, 128 thr, 4h x 4i register tile, smem-staged 16-j chunks.
// s_sT padded to stride 20 (80B) so float4 reads stay 16B-aligned.
// (frozen R15)
// ---------------------------------------------------------------------------
__global__ __launch_bounds__(128) void k_ma(const float* __restrict__ in)
{
    __shared__ float s_sT[16][20];    // score chunk transposed [j][i]
    __shared__ float s_it[16][132];   // in chunk [j][h], padded

    int tid = threadIdx.x;
    int i0  = (7 - blockIdx.x) * 16;  // heavy-first
    int b   = blockIdx.y;

    int cg = tid & 31;                // h cols cg*4..+3
    int rg = tid >> 5;                // i rows rg*4..+3
    float acc[16];
#pragma unroll
    for (int x = 0; x < 16; x++) acc[x] = 0.0f;

    int jmax = i0 + 16;
    for (int jc = 0; jc < jmax; jc += 16) {
        for (int idx = tid; idx < 256; idx += 128) {
            int r = idx >> 4, c = idx & 15;
            s_sT[c][r] = g_s[(b * TT + i0 + r) * TT + jc + c];
        }
        for (int idx = tid; idx < 16 * HH; idx += 128) {
            int j = idx >> 7, h = idx & 127;
            s_it[j][h] = in[((jc + j) * BB + b) * HH + h];
        }
        __syncthreads();
#pragma unroll
        for (int j = 0; j < 16; j++) {
            float4 sv = *(const float4*)&s_sT[j][rg * 4];    // broadcast/warp
            float4 iv = *(const float4*)&s_it[j][cg * 4];
            float svv[4] = {sv.x, sv.y, sv.z, sv.w};
            float ivv[4] = {iv.x, iv.y, iv.z, iv.w};
#pragma unroll
            for (int cc = 0; cc < 4; cc++)
#pragma unroll
                for (int rr = 0; rr < 4; rr++)
                    acc[cc * 4 + rr] = fmaf(svv[rr], ivv[cc], acc[cc * 4 + rr]);
        }
        __syncthreads();
    }
#pragma unroll
    for (int rr = 0; rr < 4; rr++) {
        int gi = i0 + rg * 4 + rr;
        float4 v = make_float4(acc[0 * 4 + rr], acc[1 * 4 + rr],
                               acc[2 * 4 + rr], acc[3 * 4 + rr]);
        *(float4*)&g_ma[(gi * BB + b) * HH + cg * 4] = v;
    }
}

// ---------------------------------------------------------------------------
// K4: predict MLP (frozen R8). grid (256, 4), 128 thr, 32 rows/block.
// ---------------------------------------------------------------------------
__global__ __launch_bounds__(128) void k_predict_mm(
    const float* __restrict__ in,
    const float* __restrict__ c0a, const float* __restrict__ c0ab,
    const float* __restrict__ c0b, const float* __restrict__ c0bb,
    const float* __restrict__ c1a, const float* __restrict__ c1ab,
    const float* __restrict__ c1b, const float* __restrict__ c1bb,
    const float* __restrict__ v0a, const float* __restrict__ v0ab,
    const float* __restrict__ v0b, const float* __restrict__ v0bb,
    const float* __restrict__ v1a, const float* __restrict__ v1ab,
    const float* __restrict__ v1b, const float* __restrict__ v1bb)
{
    __shared__ float s_in[HH][36];      // 18.4KB: inputs, then layer0 acts
    __shared__ float s_w[2][8][128];    // 8KB double-buffered weight tile

    int tid    = threadIdx.x;
    int row0   = blockIdx.x * 32;
    int pass   = blockIdx.y >> 1;
    int branch = blockIdx.y & 1;        // 0: a-side (m_a), 1: b-side (inputs)

    const float *k0, *k0bias, *k1, *k1bias;
    if (pass == 0) { k0 = branch ? c0b : c0a; k0bias = branch ? c0bb : c0ab;
                     k1 = branch ? c1b : c1a; k1bias = branch ? c1bb : c1ab; }
    else           { k0 = branch ? v0b : v0a; k0bias = branch ? v0bb : v0ab;
                     k1 = branch ? v1b : v1a; k1bias = branch ? v1bb : v1ab; }
    const float* src = branch ? in : g_ma;

    for (int idx = tid; idx < 32 * HH; idx += 128) {
        int h = idx & 127, r = idx >> 7;
        s_in[h][r] = src[(row0 + r) * HH + h];
    }

    int cg = tid & 31;
    int rg = tid >> 5;
    float a0[32];
#pragma unroll
    for (int x = 0; x < 32; x++) a0[x] = 0.0f;

    const float4* k0v = (const float4*)k0;
    float4* swv = (float4*)&s_w[0][0][0];
    swv[tid]       = k0v[(tid >> 5) * 32 + (tid & 31)];
    swv[128 + tid] = k0v[((128 + tid) >> 5) * 32 + (tid & 31)];
    __syncthreads();

    for (int t = 0; t < 16; t++) {
        int cb = t & 1, nb = cb ^ 1;
        if (t + 1 < 16) {
            int h0n = (t + 1) * 8;
#pragma unroll
            for (int kk = 0; kk < 2; kk++) {
                int lin = kk * 128 + tid;
                swv[nb * 256 + lin] = k0v[(h0n + (lin >> 5)) * 32 + (lin & 31)];
            }
        }
        int h0 = t * 8;
#pragma unroll
        for (int hl = 0; hl < 8; hl++) {
            float4 w4 = swv[cb * 256 + hl * 32 + cg];
            float4 va = *(const float4*)&s_in[h0 + hl][rg * 8];
            float4 vb = *(const float4*)&s_in[h0 + hl][rg * 8 + 4];
            float wv[4] = {w4.x, w4.y, w4.z, w4.w};
            float rv[8] = {va.x, va.y, va.z, va.w, vb.x, vb.y, vb.z, vb.w};
#pragma unroll
            for (int cc = 0; cc < 4; cc++)
#pragma unroll
                for (int rr = 0; rr < 8; rr++)
                    a0[cc * 8 + rr] = fmaf(wv[cc], rv[rr], a0[cc * 8 + rr]);
        }
        __syncthreads();
    }
    float4 b0v = *(const float4*)&k0bias[cg * 4];
    float b0[4] = {b0v.x, b0v.y, b0v.z, b0v.w};
#pragma unroll
    for (int cc = 0; cc < 4; cc++) {
        int col = cg * 4 + cc;
        float t0[8];
#pragma unroll
        for (int rr = 0; rr < 8; rr++) t0[rr] = leakyf_(a0[cc * 8 + rr] + b0[cc]);
        *(float4*)&s_in[col][rg * 8]     = make_float4(t0[0], t0[1], t0[2], t0[3]);
        *(float4*)&s_in[col][rg * 8 + 4] = make_float4(t0[4], t0[5], t0[6], t0[7]);
    }
    __syncthreads();

    int cg2 = tid & 15;
    int rg2 = tid >> 4;
    float a1[16];
#pragma unroll
    for (int x = 0; x < 16; x++) a1[x] = 0.0f;

    const float4* k1v = (const float4*)k1;
    swv[(tid >> 4) * 16 + (tid & 15)] = k1v[(tid >> 4) * 16 + (tid & 15)];
    __syncthreads();

    for (int t = 0; t < 16; t++) {
        int cb = t & 1, nb = cb ^ 1;
        if (t + 1 < 16) {
            int h0n = (t + 1) * 8;
            int hh = tid >> 4, c4 = tid & 15;
            swv[nb * 128 + hh * 16 + c4] = k1v[(h0n + hh) * 16 + c4];
        }
        int h0 = t * 8;
#pragma unroll
        for (int hl = 0; hl < 8; hl++) {
            float4 w4 = swv[cb * 128 + hl * 16 + cg2];
            float4 v4 = *(const float4*)&s_in[h0 + hl][rg2 * 4];
            float wv[4] = {w4.x, w4.y, w4.z, w4.w};
            float rv[4] = {v4.x, v4.y, v4.z, v4.w};
#pragma unroll
            for (int cc = 0; cc < 4; cc++)
#pragma unroll
                for (int rr = 0; rr < 4; rr++)
                    a1[cc * 4 + rr] = fmaf(wv[cc], rv[rr], a1[cc * 4 + rr]);
        }
        __syncthreads();
    }
    float4 b1v = *(const float4*)&k1bias[cg2 * 4];
    float b1[4] = {b1v.x, b1v.y, b1v.z, b1v.w};

    int pb = pass * 2 + branch;
#pragma unroll
    for (int cc = 0; cc < 4; cc++) {
        int cidx = cg2 * 4 + cc;
        float4 v = make_float4(leakyf_(a1[cc * 4 + 0] + b1[cc]),
                               leakyf_(a1[cc * 4 + 1] + b1[cc]),
                               leakyf_(a1[cc * 4 + 2] + b1[cc]),
                               leakyf_(a1[cc * 4 + 3] + b1[cc]));
        *(float4*)&g_l1[(pb * EE1 + cidx) * TB + row0 + rg2 * 4] = v;
    }
}

// ---------------------------------------------------------------------------
// K5: combine — dot over E1, sigmoid, pv = sig*pc (frozen R8).
// ---------------------------------------------------------------------------
__global__ __launch_bounds__(256) void k_combine(float* __restrict__ out) {
    int row = blockIdx.x * 256 + threadIdx.x;    // 0..8191
    float s0 = 0.0f, s1 = 0.0f;
#pragma unroll 8
    for (int c = 0; c < EE1; c++) {
        float a0 = g_l1[(0 * EE1 + c) * TB + row];
        float b0 = g_l1[(1 * EE1 + c) * TB + row];
        float a1 = g_l1[(2 * EE1 + c) * TB + row];
        float b1 = g_l1[(3 * EE1 + c) * TB + row];
        s0 = fmaf(a0, b0, s0);
        s1 = fmaf(a1, b1, s1);
    }
    float pc = sigmoidf_(s0);
    out[row] = pc;
    out[TB + row] = sigmoidf_(s1) * pc;
}

// ---------------------------------------------------------------------------
extern "C" void kernel_launch(void* const* d_in, const int* in_sizes, int n_in,
                              void* d_out, int out_size)
{
    (void)in_sizes; (void)n_in; (void)out_size;
    const float* in_  = (const float*)d_in[0];
    const float* w1k  = (const float*)d_in[1];
    const float* w1b  = (const float*)d_in[2];
    const float* w2k  = (const float*)d_in[3];
    const float* w3k  = (const float*)d_in[4];
    const float* w0k  = (const float*)d_in[5];
    const float* pc0a = (const float*)d_in[6];
    const float* pc0ab= (const float*)d_in[7];
    const float* pc0b = (const float*)d_in[8];
    const float* pc0bb= (const float*)d_in[9];
    const float* pc1a = (const float*)d_in[10];
    const float* pc1ab= (const float*)d_in[11];
    const float* pc1b = (const float*)d_in[12];
    const float* pc1bb= (const float*)d_in[13];
    const float* pv0a = (const float*)d_in[14];
    const float* pv0ab= (const float*)d_in[15];
    const float* pv0b = (const float*)d_in[16];
    const float* pv0bb= (const float*)d_in[17];
    const float* pv1a = (const float*)d_in[18];
    const float* pv1ab= (const float*)d_in[19];
    const float* pv1b = (const float*)d_in[20];
    const float* pv1bb= (const float*)d_in[21];
    float* out = (float*)d_out;

    k_gemm3<<<dim3(TB/32, 3), 128>>>(in_, w1k, w1b, w2k, w3k);
    k_qfixA<<<8*BH/256, 256>>>();
    k_qfixB<<<TT*BH/256, 256>>>();
    k_stile<<<dim3(10, BB), 256>>>(w0k);
    k_ma<<<dim3(8, BB), 128>>>(in_);
    k_predict_mm<<<dim3(TB/32, 4), 128>>>(in_,
        pc0a, pc0ab, pc0b, pc0bb, pc1a, pc1ab, pc1b, pc1bb,
        pv0a, pv0ab, pv0b, pv0bb, pv1a, pv1ab, pv1b, pv1bb);
    k_combine<<<TB/256, 256>>>(out);
}

// round 17
// speedup vs baseline: 1.0136x; 1.0136x over previous
#include <cuda_runtime.h>

#define TT 128
#define BB 64
#define HH 128
#define EE0 128
#define EE1 64
#define TB (TT*BB)
#define BH (BB*HH)
#define LOG2E 1.4426950408889634f

// Scratch (device globals: no allocation allowed in kernel_launch)
__device__ float g_x1T[BB*HH*TT];   // x1 transposed [B,H,T]
__device__ float g_q[TT*BB*HH];     // x2, then q = x2 + cum(y)/(t+1)
__device__ float g_y[TT*BB*HH];     // in@w3, then in-chunk prefix sums
__device__ float g_ps[8*BH];        // per-chunk totals
__device__ float g_s[BB*TT*TT];     // scores [b][i][j] (diagonal-masked)
__device__ float g_ma[TT*BB*HH];    // m_a           [T,B,H]
__device__ float g_l1[4*EE1*TB];    // layer1 outs [pass*2+branch][c][row]

__device__ __forceinline__ float fex2(float x){ float r; asm("ex2.approx.f32 %0, %1;" : "=f"(r) : "f"(x)); return r; }
__device__ __forceinline__ float frcp(float x){ float r; asm("rcp.approx.f32 %0, %1;" : "=f"(r) : "f"(x)); return r; }
__device__ __forceinline__ float ftanh(float x){ float r; asm("tanh.approx.f32 %0, %1;" : "=f"(r) : "f"(x)); return r; }
__device__ __forceinline__ float sigmoidf_(float x){ return frcp(1.0f + fex2(x * -LOG2E)); }
__device__ __forceinline__ float leakyf_(float x){ return x > 0.0f ? x : 0.3f * x; }

// ---------------------------------------------------------------------------
// K1: triple GEMM, uniform K=128. grid (256, 3), 128 thr, 32 rows/block.
// (frozen R11)
// ---------------------------------------------------------------------------
__global__ __launch_bounds__(128) void k_gemm3(
    const float* __restrict__ in,
    const float* __restrict__ w1, const float* __restrict__ w1b,
    const float* __restrict__ w2, const float* __restrict__ w3)
{
    __shared__ float s_in[HH][36];      // 18.4KB input tile transposed
    __shared__ float s_w[2][8][128];    // 8KB double-buffered weight tile

    int tid  = threadIdx.x;
    int row0 = blockIdx.x * 32;
    int y    = blockIdx.y;              // 0: x1, 1: x2, 2: y

    const float* wsel = (y == 0) ? w1 : (y == 1) ? w2 : w3;

    for (int idx = tid; idx < 32 * HH; idx += 128) {
        int h = idx & 127, r = idx >> 7;
        s_in[h][r] = in[(row0 + r) * HH + h];
    }

    int cg = tid & 31;               // cols cg*4 .. cg*4+3  (== lane)
    int rg = tid >> 5;               // rows rg*8 .. rg*8+7  (== warp)
    float a0[32];
#pragma unroll
    for (int x = 0; x < 32; x++) a0[x] = 0.0f;

    const float4* kv = (const float4*)wsel;
    float4* swv = (float4*)&s_w[0][0][0];  // [2][8][32] float4 view
    swv[tid]       = kv[(tid >> 5) * 32 + (tid & 31)];
    swv[128 + tid] = kv[((128 + tid) >> 5) * 32 + (tid & 31)];
    __syncthreads();

    for (int t = 0; t < 16; t++) {
        int cb = t & 1, nb = cb ^ 1;
        if (t + 1 < 16) {
            int h0n = (t + 1) * 8;
#pragma unroll
            for (int kk = 0; kk < 2; kk++) {
                int lin = kk * 128 + tid;
                swv[nb * 256 + lin] = kv[(h0n + (lin >> 5)) * 32 + (lin & 31)];
            }
        }
        int h0 = t * 8;
#pragma unroll
        for (int hl = 0; hl < 8; hl++) {
            float4 w4 = swv[cb * 256 + hl * 32 + cg];
            float4 va = *(const float4*)&s_in[h0 + hl][rg * 8];
            float4 vb = *(const float4*)&s_in[h0 + hl][rg * 8 + 4];
            float wv[4] = {w4.x, w4.y, w4.z, w4.w};
            float rv[8] = {va.x, va.y, va.z, va.w, vb.x, vb.y, vb.z, vb.w};
#pragma unroll
            for (int cc = 0; cc < 4; cc++)
#pragma unroll
                for (int rr = 0; rr < 8; rr++)
                    a0[cc * 8 + rr] = fmaf(wv[cc], rv[rr], a0[cc * 8 + rr]);
        }
        __syncthreads();
    }

    if (y == 0) {
        float4 bv = *(const float4*)&w1b[cg * 4];
        float bb[4] = {bv.x, bv.y, bv.z, bv.w};
#pragma unroll
        for (int cc = 0; cc < 4; cc++) {
            int col = cg * 4 + cc;
#pragma unroll
            for (int rr = 0; rr < 8; rr++) {
                int grow = row0 + rg * 8 + rr;
                int tt = grow >> 6;       // row = t*B + b
                int b  = grow & 63;
                g_x1T[(b * HH + col) * TT + tt] = a0[cc * 8 + rr] + bb[cc];
            }
        }
    } else {
        float* dst = (y == 1) ? g_q : g_y;
#pragma unroll
        for (int rr = 0; rr < 8; rr++) {
            int grow = row0 + rg * 8 + rr;
            float4 v = make_float4(a0[0 * 8 + rr], a0[1 * 8 + rr],
                                   a0[2 * 8 + rr], a0[3 * 8 + rr]);
            *(float4*)&dst[grow * HH + cg * 4] = v;   // coalesced STG.128
        }
    }
}

// ---------------------------------------------------------------------------
// K2a: scan phase A (frozen R11).
// ---------------------------------------------------------------------------
__global__ __launch_bounds__(256) void k_qfixA() {
    int gid = blockIdx.x * 256 + threadIdx.x;   // 0..65535
    int c   = gid >> 13;                        // chunk 0..7
    int idx = gid & (BH - 1);                   // (b,h) 0..8191
    float acc = 0.0f;
#pragma unroll
    for (int k = 0; k < 16; k++) {
        int t = c * 16 + k;
        acc += g_y[t * BH + idx];
        g_y[t * BH + idx] = acc;                // local prefix incl. current
    }
    g_ps[c * BH + idx] = acc;                   // chunk total
}

// ---------------------------------------------------------------------------
// K2b: scan phase B (frozen R11).
// ---------------------------------------------------------------------------
__global__ __launch_bounds__(256) void k_qfixB() {
    int gid = blockIdx.x * 256 + threadIdx.x;   // 0..2^20-1
    int t   = gid >> 13;
    int idx = gid & (BH - 1);
    int c   = t >> 4;
    float off = 0.0f;
    for (int cc = 0; cc < c; cc++)
        off += g_ps[cc * BH + idx];
    float cum = off + g_y[gid];
    g_q[gid] += cum / (float)(t + 1);
}

// ---------------------------------------------------------------------------
// K3a v3: score tiles, 32x32, h-CHUNKED (2 x 64) to halve smem (~19KB) and
// lift occupancy to the register limit (~6 blocks/SM, 75% occ).
// grid (10, 64) triangular; 256 thr = 1 i x 4 contiguous j each.
// Inner loop per h: 1 LDS.128 + 2 bcast LDS + 4x(FADD+tanh+FMA).
// ---------------------------------------------------------------------------
__global__ __launch_bounds__(256) void k_stile(const float* __restrict__ w0)
{
    __shared__ float sx1T[64][36];    // 0.5*x1 chunk, [h-local][j-local]
    __shared__ float sqT[64][36];     // 0.5*q  chunk, [h-local][i-local]
    __shared__ float w0s[HH];
    __shared__ float w0sum_sh;

    int tid = threadIdx.x;
    int b   = blockIdx.y;
    // triangular enumeration over 4 tile-rows: bx -> (it, jt), jt <= it
    int it = 0, x = blockIdx.x;
    while (x > it) { x -= it + 1; it++; }
    int jt = x;
    int i0 = it * 32, j0 = jt * 32;

    // w0 load + reduce (once)
    if (tid < 128) w0s[tid] = w0[tid];
    __syncthreads();
    if (tid < 32) {
        float s = w0s[tid] + w0s[tid+32] + w0s[tid+64] + w0s[tid+96];
#pragma unroll
        for (int off = 16; off; off >>= 1) s += __shfl_xor_sync(0xFFFFFFFFu, s, off);
        if (tid == 0) w0sum_sh = s;
    }

    int jq = tid & 7;                 // j group: cols jq*4 .. jq*4+3
    int il = tid >> 3;                // i row 0..31
    float acc[4] = {0.0f, 0.0f, 0.0f, 0.0f};

    const float* xb = g_x1T + b * (HH * TT) + j0;

    for (int hc = 0; hc < 2; hc++) {
        int h0 = hc * 64;
        __syncthreads();              // prior chunk reads (or w0 init) done
        // x1 chunk: 64 h x 32 j (coalesced 128B rows)
        for (int idx = tid; idx < 64 * 32; idx += 256) {
            int hl = idx >> 5, jl = idx & 31;
            sx1T[hl][jl] = xb[(h0 + hl) * TT + jl] * 0.5f;
        }
        // q chunk: 32 i x 64 h (coalesced 256B segments), write transposed
        for (int idx = tid; idx < 32 * 64; idx += 256) {
            int il2 = idx >> 6, hh = idx & 63;
            sqT[hh][il2] = g_q[((i0 + il2) * BB + b) * HH + h0 + hh] * 0.5f;
        }
        __syncthreads();
#pragma unroll 4
        for (int hl = 0; hl < 64; hl++) {
            float4 x4 = *(const float4*)&sx1T[hl][jq * 4];  // conflict-free
            float qv  = sqT[hl][il];                        // broadcast
            float wv  = w0s[h0 + hl];                       // broadcast
            acc[0] = fmaf(wv, ftanh(x4.x + qv), acc[0]);
            acc[1] = fmaf(wv, ftanh(x4.y + qv), acc[1]);
            acc[2] = fmaf(wv, ftanh(x4.z + qv), acc[2]);
            acc[3] = fmaf(wv, ftanh(x4.w + qv), acc[3]);
        }
    }
    float w0sum = w0sum_sh;
    int gi = i0 + il;
    int gjb = j0 + jq * 4;
    float4 v;
    v.x = (gjb + 0 <= gi) ? 0.5f * (acc[0] + w0sum) : 0.0f;
    v.y = (gjb + 1 <= gi) ? 0.5f * (acc[1] + w0sum) : 0.0f;
    v.z = (gjb + 2 <= gi) ? 0.5f * (acc[2] + w0sum) : 0.0f;
    v.w = (gjb + 3 <= gi) ? 0.5f * (acc[3] + w0sum) : 0.0f;
    *(float4*)&g_s[(b * TT + gi) * TT + gjb] = v;       // coalesced STG.128
}

// ---------------------------------------------------------------------------
// K3b: m_a = scores @ in (batched triangular GEMM, frozen R15).
// ---------------------------------------------------------------------------
__global__ __launch_bounds__(128) void k_ma(const float* __restrict__ in)
{
    __shared__ float s_sT[16][20];    // score chunk transposed [j][i]
    __shared__ float s_it[16][132];   // in chunk [j][h], padded

    int tid = threadIdx.x;
    int i0  = (7 - blockIdx.x) * 16;  // heavy-first
    int b   = blockIdx.y;

    int cg = tid & 31;                // h cols cg*4..+3
    int rg = tid >> 5;                // i rows rg*4..+3
    float acc[16];
#pragma unroll
    for (int x = 0; x < 16; x++) acc[x] = 0.0f;

    int jmax = i0 + 16;
    for (int jc = 0; jc < jmax; jc += 16) {
        for (int idx = tid; idx < 256; idx += 128) {
            int r = idx >> 4, c = idx & 15;
            s_sT[c][r] = g_s[(b * TT + i0 + r) * TT + jc + c];
        }
        for (int idx = tid; idx < 16 * HH; idx += 128) {
            int j = idx >> 7, h = idx & 127;
            s_it[j][h] = in[((jc + j) * BB + b) * HH + h];
        }
        __syncthreads();
#pragma unroll
        for (int j = 0; j < 16; j++) {
            float4 sv = *(const float4*)&s_sT[j][rg * 4];    // broadcast/warp
            float4 iv = *(const float4*)&s_it[j][cg * 4];
            float svv[4] = {sv.x, sv.y, sv.z, sv.w};
            float ivv[4] = {iv.x, iv.y, iv.z, iv.w};
#pragma unroll
            for (int cc = 0; cc < 4; cc++)
#pragma unroll
                for (int rr = 0; rr < 4; rr++)
                    acc[cc * 4 + rr] = fmaf(svv[rr], ivv[cc], acc[cc * 4 + rr]);
        }
        __syncthreads();
    }
#pragma unroll
    for (int rr = 0; rr < 4; rr++) {
        int gi = i0 + rg * 4 + rr;
        float4 v = make_float4(acc[0 * 4 + rr], acc[1 * 4 + rr],
                               acc[2 * 4 + rr], acc[3 * 4 + rr]);
        *(float4*)&g_ma[(gi * BB + b) * HH + cg * 4] = v;
    }
}

// ---------------------------------------------------------------------------
// K4: predict MLP (frozen R8). grid (256, 4), 128 thr, 32 rows/block.
// ---------------------------------------------------------------------------
__global__ __launch_bounds__(128) void k_predict_mm(
    const float* __restrict__ in,
    const float* __restrict__ c0a, const float* __restrict__ c0ab,
    const float* __restrict__ c0b, const float* __restrict__ c0bb,
    const float* __restrict__ c1a, const float* __restrict__ c1ab,
    const float* __restrict__ c1b, const float* __restrict__ c1bb,
    const float* __restrict__ v0a, const float* __restrict__ v0ab,
    const float* __restrict__ v0b, const float* __restrict__ v0bb,
    const float* __restrict__ v1a, const float* __restrict__ v1ab,
    const float* __restrict__ v1b, const float* __restrict__ v1bb)
{
    __shared__ float s_in[HH][36];      // 18.4KB: inputs, then layer0 acts
    __shared__ float s_w[2][8][128];    // 8KB double-buffered weight tile

    int tid    = threadIdx.x;
    int row0   = blockIdx.x * 32;
    int pass   = blockIdx.y >> 1;
    int branch = blockIdx.y & 1;        // 0: a-side (m_a), 1: b-side (inputs)

    const float *k0, *k0bias, *k1, *k1bias;
    if (pass == 0) { k0 = branch ? c0b : c0a; k0bias = branch ? c0bb : c0ab;
                     k1 = branch ? c1b : c1a; k1bias = branch ? c1bb : c1ab; }
    else           { k0 = branch ? v0b : v0a; k0bias = branch ? v0bb : v0ab;
                     k1 = branch ? v1b : v1a; k1bias = branch ? v1bb : v1ab; }
    const float* src = branch ? in : g_ma;

    for (int idx = tid; idx < 32 * HH; idx += 128) {
        int h = idx & 127, r = idx >> 7;
        s_in[h][r] = src[(row0 + r) * HH + h];
    }

    int cg = tid & 31;
    int rg = tid >> 5;
    float a0[32];
#pragma unroll
    for (int x = 0; x < 32; x++) a0[x] = 0.0f;

    const float4* k0v = (const float4*)k0;
    float4* swv = (float4*)&s_w[0][0][0];
    swv[tid]       = k0v[(tid >> 5) * 32 + (tid & 31)];
    swv[128 + tid] = k0v[((128 + tid) >> 5) * 32 + (tid & 31)];
    __syncthreads();

    for (int t = 0; t < 16; t++) {
        int cb = t & 1, nb = cb ^ 1;
        if (t + 1 < 16) {
            int h0n = (t + 1) * 8;
#pragma unroll
            for (int kk = 0; kk < 2; kk++) {
                int lin = kk * 128 + tid;
                swv[nb * 256 + lin] = k0v[(h0n + (lin >> 5)) * 32 + (lin & 31)];
            }
        }
        int h0 = t * 8;
#pragma unroll
        for (int hl = 0; hl < 8; hl++) {
            float4 w4 = swv[cb * 256 + hl * 32 + cg];
            float4 va = *(const float4*)&s_in[h0 + hl][rg * 8];
            float4 vb = *(const float4*)&s_in[h0 + hl][rg * 8 + 4];
            float wv[4] = {w4.x, w4.y, w4.z, w4.w};
            float rv[8] = {va.x, va.y, va.z, va.w, vb.x, vb.y, vb.z, vb.w};
#pragma unroll
            for (int cc = 0; cc < 4; cc++)
#pragma unroll
                for (int rr = 0; rr < 8; rr++)
                    a0[cc * 8 + rr] = fmaf(wv[cc], rv[rr], a0[cc * 8 + rr]);
        }
        __syncthreads();
    }
    float4 b0v = *(const float4*)&k0bias[cg * 4];
    float b0[4] = {b0v.x, b0v.y, b0v.z, b0v.w};
#pragma unroll
    for (int cc = 0; cc < 4; cc++) {
        int col = cg * 4 + cc;
        float t0[8];
#pragma unroll
        for (int rr = 0; rr < 8; rr++) t0[rr] = leakyf_(a0[cc * 8 + rr] + b0[cc]);
        *(float4*)&s_in[col][rg * 8]     = make_float4(t0[0], t0[1], t0[2], t0[3]);
        *(float4*)&s_in[col][rg * 8 + 4] = make_float4(t0[4], t0[5], t0[6], t0[7]);
    }
    __syncthreads();

    int cg2 = tid & 15;
    int rg2 = tid >> 4;
    float a1[16];
#pragma unroll
    for (int x = 0; x < 16; x++) a1[x] = 0.0f;

    const float4* k1v = (const float4*)k1;
    swv[(tid >> 4) * 16 + (tid & 15)] = k1v[(tid >> 4) * 16 + (tid & 15)];
    __syncthreads();

    for (int t = 0; t < 16; t++) {
        int cb = t & 1, nb = cb ^ 1;
        if (t + 1 < 16) {
            int h0n = (t + 1) * 8;
            int hh = tid >> 4, c4 = tid & 15;
            swv[nb * 128 + hh * 16 + c4] = k1v[(h0n + hh) * 16 + c4];
        }
        int h0 = t * 8;
#pragma unroll
        for (int hl = 0; hl < 8; hl++) {
            float4 w4 = swv[cb * 128 + hl * 16 + cg2];
            float4 v4 = *(const float4*)&s_in[h0 + hl][rg2 * 4];
            float wv[4] = {w4.x, w4.y, w4.z, w4.w};
            float rv[4] = {v4.x, v4.y, v4.z, v4.w};
#pragma unroll
            for (int cc = 0; cc < 4; cc++)
#pragma unroll
                for (int rr = 0; rr < 4; rr++)
                    a1[cc * 4 + rr] = fmaf(wv[cc], rv[rr], a1[cc * 4 + rr]);
        }
        __syncthreads();
    }
    float4 b1v = *(const float4*)&k1bias[cg2 * 4];
    float b1[4] = {b1v.x, b1v.y, b1v.z, b1v.w};

    int pb = pass * 2 + branch;
#pragma unroll
    for (int cc = 0; cc < 4; cc++) {
        int cidx = cg2 * 4 + cc;
        float4 v = make_float4(leakyf_(a1[cc * 4 + 0] + b1[cc]),
                               leakyf_(a1[cc * 4 + 1] + b1[cc]),
                               leakyf_(a1[cc * 4 + 2] + b1[cc]),
                               leakyf_(a1[cc * 4 + 3] + b1[cc]));
        *(float4*)&g_l1[(pb * EE1 + cidx) * TB + row0 + rg2 * 4] = v;
    }
}

// ---------------------------------------------------------------------------
// K5: combine — dot over E1, sigmoid, pv = sig*pc (frozen R8).
// ---------------------------------------------------------------------------
__global__ __launch_bounds__(256) void k_combine(float* __restrict__ out) {
    int row = blockIdx.x * 256 + threadIdx.x;    // 0..8191
    float s0 = 0.0f, s1 = 0.0f;
#pragma unroll 8
    for (int c = 0; c < EE1; c++) {
        float a0 = g_l1[(0 * EE1 + c) * TB + row];
        float b0 = g_l1[(1 * EE1 + c) * TB + row];
        float a1 = g_l1[(2 * EE1 + c) * TB + row];
        float b1 = g_l1[(3 * EE1 + c) * TB + row];
        s0 = fmaf(a0, b0, s0);
        s1 = fmaf(a1, b1, s1);
    }
    float pc = sigmoidf_(s0);
    out[row] = pc;
    out[TB + row] = sigmoidf_(s1) * pc;
}

// ---------------------------------------------------------------------------
extern "C" void kernel_launch(void* const* d_in, const int* in_sizes, int n_in,
                              void* d_out, int out_size)
{
    (void)in_sizes; (void)n_in; (void)out_size;
    const float* in_  = (const float*)d_in[0];
    const float* w1k  = (const float*)d_in[1];
    const float* w1b  = (const float*)d_in[2];
    const float* w2k  = (const float*)d_in[3];
    const float* w3k  = (const float*)d_in[4];
    const float* w0k  = (const float*)d_in[5];
    const float* pc0a = (const float*)d_in[6];
    const float* pc0ab= (const float*)d_in[7];
    const float* pc0b = (const float*)d_in[8];
    const float* pc0bb= (const float*)d_in[9];
    const float* pc1a = (const float*)d_in[10];
    const float* pc1ab= (const float*)d_in[11];
    const float* pc1b = (const float*)d_in[12];
    const float* pc1bb= (const float*)d_in[13];
    const float* pv0a = (const float*)d_in[14];
    const float* pv0ab= (const float*)d_in[15];
    const float* pv0b = (const float*)d_in[16];
    const float* pv0bb= (const float*)d_in[17];
    const float* pv1a = (const float*)d_in[18];
    const float* pv1ab= (const float*)d_in[19];
    const float* pv1b = (const float*)d_in[20];
    const float* pv1bb= (const float*)d_in[21];
    float* out = (float*)d_out;

    k_gemm3<<<dim3(TB/32, 3), 128>>>(in_, w1k, w1b, w2k, w3k);
    k_qfixA<<<8*BH/256, 256>>>();
    k_qfixB<<<TT*BH/256, 256>>>();
    k_stile<<<dim3(10, BB), 256>>>(w0k);
    k_ma<<<dim3(8, BB), 128>>>(in_);
    k_predict_mm<<<dim3(TB/32, 4), 128>>>(in_,
        pc0a, pc0ab, pc0b, pc0bb, pc1a, pc1ab, pc1b, pc1bb,
        pv0a, pv0ab, pv0b, pv0bb, pv1a, pv1ab, pv1b, pv1bb);
    k_combine<<<TB/256, 256>>>(out);
}